// round 6
// baseline (speedup 1.0000x reference)
#include <cuda_runtime.h>
#include <cstdint>

// 24-qubit state-vector sim, 8 two-qubit gates, step s -> qubits (s, s+7).
// SINGLE PASS via 2-CTA cluster: cluster tile = amp bits 0..14; each CTA
// holds bits 0..13 (16384 amps, 128KB smem), bit 14 = cluster rank.
// Gates 0..5 fused as register pairs, gate 6 local, gate 7 (bits 7,14)
// exchanged through DSMEM between cluster barriers. 256MB total DRAM traffic.

#define NSTATE (1u << 24)
typedef unsigned long long u64;

__device__ __forceinline__ u64 pk2(float lo, float hi) {
    u64 r; asm("mov.b64 %0, {%1, %2};" : "=l"(r) : "f"(lo), "f"(hi)); return r;
}
__device__ __forceinline__ void upk2(u64 v, float& lo, float& hi) {
    asm("mov.b64 {%0, %1}, %2;" : "=f"(lo), "=f"(hi) : "l"(v));
}
__device__ __forceinline__ u64 ffma2(u64 a, u64 b, u64 c) {
    u64 d; asm("fma.rn.f32x2 %0, %1, %2, %3;" : "=l"(d) : "l"(a), "l"(b), "l"(c)); return d;
}
__device__ __forceinline__ u64 fmul2(u64 a, u64 b) {
    u64 d; asm("mul.rn.f32x2 %0, %1, %2;" : "=l"(d) : "l"(a), "l"(b)); return d;
}
__device__ __forceinline__ float negf(float v) {
    return __int_as_float(__float_as_int(v) ^ 0x80000000u);
}
// Half-warp conflict-free swizzle: fold bit4 -> bits{0,2}, bit5 -> bits{1,3}.
__device__ __forceinline__ unsigned SWZ(unsigned x) {
    return x ^ (((x >> 4) & 1u) * 5u) ^ (((x >> 5) & 1u) * 10u);
}
__device__ __forceinline__ void cluster_barrier() {
    asm volatile("barrier.cluster.arrive.aligned;" ::: "memory");
    asm volatile("barrier.cluster.wait.aligned;" ::: "memory");
}

// Complex 4x4 gate on a quad of packed (re,im) amps.
// q_h = (-si, sr); acc = sum_h p_h*(wr,wr) + q_h*(wi,wi). 8 ffma2/output.
__device__ __forceinline__ void gate_quad(u64& v0, u64& v1, u64& v2, u64& v3,
                                          const u64* __restrict__ wa,
                                          const u64* __restrict__ wb)
{
    float r0,i0,r1,i1,r2,i2,r3,i3;
    upk2(v0,r0,i0); upk2(v1,r1,i1); upk2(v2,r2,i2); upk2(v3,r3,i3);
    u64 q0 = pk2(negf(i0), r0), q1 = pk2(negf(i1), r1);
    u64 q2 = pk2(negf(i2), r2), q3 = pk2(negf(i3), r3);
    u64 o[4];
    #pragma unroll
    for (int g = 0; g < 4; ++g) {
        u64 acc = fmul2(v0, wa[g*4+0]);
        acc = ffma2(q0, wb[g*4+0], acc);
        acc = ffma2(v1, wa[g*4+1], acc);
        acc = ffma2(q1, wb[g*4+1], acc);
        acc = ffma2(v2, wa[g*4+2], acc);
        acc = ffma2(q2, wb[g*4+2], acc);
        acc = ffma2(v3, wa[g*4+3], acc);
        acc = ffma2(q3, wb[g*4+3], acc);
        o[g] = acc;
    }
    v0 = o[0]; v1 = o[1]; v2 = o[2]; v3 = o[3];
}

// Two fused gates on a 16-amp supergroup. P0..P3 = inserted tile-bit positions
// (ascending). Gate0 varies group bits (0,2) = tile bits (P0,P2); gate1 varies
// (1,3) = (P1,P3). All amp-array indices are literal constants.
template <int P0, int P1, int P2, int P3>
__device__ __forceinline__ void apply_pair_sg(float2* sm, unsigned sg,
                                              const u64* __restrict__ w0,
                                              const u64* __restrict__ w1)
{
    unsigned x = sg;
    x = ((x & ~((1u << P0) - 1u)) << 1) | (x & ((1u << P0) - 1u));
    x = ((x & ~((1u << P1) - 1u)) << 1) | (x & ((1u << P1) - 1u));
    x = ((x & ~((1u << P2) - 1u)) << 1) | (x & ((1u << P2) - 1u));
    x = ((x & ~((1u << P3) - 1u)) << 1) | (x & ((1u << P3) - 1u));

    u64 p[16];
    #pragma unroll
    for (int i = 0; i < 16; ++i) {
        unsigned off = ((i & 1)        ? (1u << P0) : 0u)
                     | (((i >> 1) & 1) ? (1u << P1) : 0u)
                     | (((i >> 2) & 1) ? (1u << P2) : 0u)
                     | (((i >> 3) & 1) ? (1u << P3) : 0u);
        float2 v = sm[SWZ(x | off)];
        p[i] = pk2(v.x, v.y);
    }

    gate_quad(p[0],  p[1],  p[4],  p[5],  w0, w0 + 16);
    gate_quad(p[2],  p[3],  p[6],  p[7],  w0, w0 + 16);
    gate_quad(p[8],  p[9],  p[12], p[13], w0, w0 + 16);
    gate_quad(p[10], p[11], p[14], p[15], w0, w0 + 16);

    gate_quad(p[0], p[2], p[8],  p[10], w1, w1 + 16);
    gate_quad(p[1], p[3], p[9],  p[11], w1, w1 + 16);
    gate_quad(p[4], p[6], p[12], p[14], w1, w1 + 16);
    gate_quad(p[5], p[7], p[13], p[15], w1, w1 + 16);

    #pragma unroll
    for (int i = 0; i < 16; ++i) {
        unsigned off = ((i & 1)        ? (1u << P0) : 0u)
                     | (((i >> 1) & 1) ? (1u << P1) : 0u)
                     | (((i >> 2) & 1) ? (1u << P2) : 0u)
                     | (((i >> 3) & 1) ? (1u << P3) : 0u);
        float lo, hi; upk2(p[i], lo, hi);
        sm[SWZ(x | off)] = make_float2(lo, hi);
    }
}

__global__ __launch_bounds__(512) __cluster_dims__(2, 1, 1)
void qsim_all(const float* __restrict__ in, float* __restrict__ out,
              const float* __restrict__ gates)
{
    extern __shared__ float2 sm[];   // 16384 amps = 128 KB
    __shared__ u64 sW[8][32];        // per gate: [0..15]=(wr,wr), [16..31]=(wi,wi)

    const unsigned t = threadIdx.x;
    const unsigned gofs = blockIdx.x << 14;   // amp bits 14..23 (bit14 = rank)

    if (t < 256) {
        unsigned gate = t >> 5, idx = t & 31, k = idx & 15;
        float w = (idx < 16) ? gates[gate * 32 + k] : gates[gate * 32 + 16 + k];
        sW[gate][idx] = pk2(w, w);
    }

    // ---- Stage: contiguous LDG.128 per plane ----
    #pragma unroll
    for (int j = 0; j < 8; ++j) {
        unsigned a = (t + 512u * j) * 4u;
        float4 r4 = *(const float4*)(in + (gofs | a));
        float4 m4 = *(const float4*)(in + NSTATE + (gofs | a));
        sm[SWZ(a + 0)] = make_float2(r4.x, m4.x);
        sm[SWZ(a + 1)] = make_float2(r4.y, m4.y);
        sm[SWZ(a + 2)] = make_float2(r4.z, m4.z);
        sm[SWZ(a + 3)] = make_float2(r4.w, m4.w);
    }
    __syncthreads();

    // ---- Gates 0..5 as three register-fused pairs (1024 supergroups each) ----
    apply_pair_sg<0, 1, 7, 8>(sm, t,        sW[0], sW[1]);
    apply_pair_sg<0, 1, 7, 8>(sm, t + 512u, sW[0], sW[1]);
    __syncthreads();
    apply_pair_sg<2, 3, 9, 10>(sm, t,        sW[2], sW[3]);
    apply_pair_sg<2, 3, 9, 10>(sm, t + 512u, sW[2], sW[3]);
    __syncthreads();
    apply_pair_sg<4, 5, 11, 12>(sm, t,        sW[4], sW[5]);
    apply_pair_sg<4, 5, 11, 12>(sm, t + 512u, sW[4], sW[5]);
    __syncthreads();

    // ---- Gate 6: bits (6,13), CTA-local ----
    #pragma unroll
    for (int k = 0; k < 8; ++k) {
        unsigned xg = t + 512u * k;                       // 4096 groups
        unsigned y = ((xg & ~63u) << 1) | (xg & 63u);     // insert 0 at bit 6
        unsigned i0 = SWZ(y), i1 = SWZ(y | 64u);
        unsigned i2 = SWZ(y | 8192u), i3 = SWZ(y | 8192u | 64u);
        float2 a = sm[i0], b = sm[i1], c = sm[i2], d = sm[i3];
        u64 v0 = pk2(a.x, a.y), v1 = pk2(b.x, b.y);
        u64 v2 = pk2(c.x, c.y), v3 = pk2(d.x, d.y);
        gate_quad(v0, v1, v2, v3, sW[6], sW[6] + 16);
        float lo, hi;
        upk2(v0, lo, hi); sm[i0] = make_float2(lo, hi);
        upk2(v1, lo, hi); sm[i1] = make_float2(lo, hi);
        upk2(v2, lo, hi); sm[i2] = make_float2(lo, hi);
        upk2(v3, lo, hi); sm[i3] = make_float2(lo, hi);
    }

    cluster_barrier();   // gate-6 results visible cluster-wide

    // ---- Gate 7: bits (7,14). Groups partitioned by parity; each CTA computes
    //      all 4 outputs for its groups, exchanging 2 amps with the peer. ----
    unsigned rank;
    asm("mov.u32 %0, %%cluster_ctarank;" : "=r"(rank));
    uint32_t base;
    asm("{ .reg .u64 tt; cvta.to.shared.u64 tt, %1; cvt.u32.u64 %0, tt; }"
        : "=r"(base) : "l"(sm));
    uint32_t pbase;
    asm("mapa.shared::cluster.u32 %0, %1, %2;" : "=r"(pbase) : "r"(base), "r"(rank ^ 1u));

    #pragma unroll
    for (int k = 0; k < 8; ++k) {
        unsigned xg = ((t + 512u * k) << 1) | rank;       // 13-bit group id, bit0 = rank
        unsigned x = ((xg & ~127u) << 1) | (xg & 127u);   // insert 0 at bit 7
        unsigned j0 = SWZ(x), j1 = SWZ(x | 128u);
        float2 l0 = sm[j0], l1 = sm[j1];
        u64 L0 = pk2(l0.x, l0.y), L1 = pk2(l1.x, l1.y);   // h = 2*rank, 2*rank+1
        u64 P0, P1;                                        // peer: h = 2*!rank, +1
        asm volatile("ld.shared::cluster.b64 %0, [%1];" : "=l"(P0) : "r"(pbase + j0 * 8u));
        asm volatile("ld.shared::cluster.b64 %0, [%1];" : "=l"(P1) : "r"(pbase + j1 * 8u));
        u64 a0 = rank ? P0 : L0, a1 = rank ? P1 : L1;     // h-ordered inputs
        u64 a2 = rank ? L0 : P0, a3 = rank ? L1 : P1;
        gate_quad(a0, a1, a2, a3, sW[7], sW[7] + 16);
        u64 m0 = rank ? a2 : a0, m1 = rank ? a3 : a1;     // my outputs
        u64 e0 = rank ? a0 : a2, e1 = rank ? a1 : a3;     // peer outputs
        float lo, hi;
        upk2(m0, lo, hi); sm[j0] = make_float2(lo, hi);
        upk2(m1, lo, hi); sm[j1] = make_float2(lo, hi);
        asm volatile("st.shared::cluster.b64 [%0], %1;" :: "r"(pbase + j0 * 8u), "l"(e0) : "memory");
        asm volatile("st.shared::cluster.b64 [%0], %1;" :: "r"(pbase + j1 * 8u), "l"(e1) : "memory");
    }

    cluster_barrier();   // all gate-7 writes (incl. peer stores) complete

    // ---- Writeout: contiguous STG.128 per plane ----
    #pragma unroll
    for (int j = 0; j < 8; ++j) {
        unsigned a = (t + 512u * j) * 4u;
        float2 v0 = sm[SWZ(a + 0)], v1 = sm[SWZ(a + 1)];
        float2 v2 = sm[SWZ(a + 2)], v3 = sm[SWZ(a + 3)];
        *(float4*)(out + (gofs | a))          = make_float4(v0.x, v1.x, v2.x, v3.x);
        *(float4*)(out + NSTATE + (gofs | a)) = make_float4(v0.y, v1.y, v2.y, v3.y);
    }
}

extern "C" void kernel_launch(void* const* d_in, const int* in_sizes, int n_in,
                              void* d_out, int out_size)
{
    const float* state = (const float*)d_in[0];   // 2 * 2^24 floats (re, im planes)
    const float* gates = (const float*)d_in[1];   // 8 * 2 * 4 * 4 floats
    float* out = (float*)d_out;

    const int smem_bytes = 16384 * sizeof(float2);   // 128 KB dynamic
    cudaFuncSetAttribute(qsim_all, cudaFuncAttributeMaxDynamicSharedMemorySize, smem_bytes);
    qsim_all<<<1024, 512, smem_bytes>>>(state, out, gates);
}

// round 7
// speedup vs baseline: 1.9309x; 1.9309x over previous
#include <cuda_runtime.h>

// 24-qubit state-vector sim, 8 two-qubit gates, step s -> qubits (s, s+7).
// Two passes of 4 gates; gates fused in PAIRS in registers (16-amp supergroup
// per thread, weights in registers). R7 = R3 champion structure with:
//  (1) corrected bank swizzle: SWZ(x) = x ^ x4*0b0101 ^ x5*0b1010 -- rank-4
//      (conflict-free) at 16-lane phase granularity for EVERY access pattern
//      (staging, writeout, all four pair patterns). R3's swizzle dropped
//      lane bit t2 from the bank bits -> 2-way conflicts everywhere.
//  (2) complex MAC via q=(-si,sr) per input (ALU XOR) instead of per-output
//      combine (2 FADDs on the fma pipe): 8 ffma2/output flat, no combine.

#define NSTATE (1u << 24)
typedef unsigned long long u64;

__device__ __forceinline__ u64 pk2(float lo, float hi) {
    u64 r; asm("mov.b64 %0, {%1, %2};" : "=l"(r) : "f"(lo), "f"(hi)); return r;
}
__device__ __forceinline__ void upk2(u64 v, float& lo, float& hi) {
    asm("mov.b64 {%0, %1}, %2;" : "=f"(lo), "=f"(hi) : "l"(v));
}
__device__ __forceinline__ u64 ffma2(u64 a, u64 b, u64 c) {
    u64 d; asm("fma.rn.f32x2 %0, %1, %2, %3;" : "=l"(d) : "l"(a), "l"(b), "l"(c)); return d;
}
__device__ __forceinline__ u64 fmul2(u64 a, u64 b) {
    u64 d; asm("mul.rn.f32x2 %0, %1, %2;" : "=l"(d) : "l"(a), "l"(b)); return d;
}
__device__ __forceinline__ float negf(float v) {
    return __int_as_float(__float_as_int(v) ^ 0x80000000u);
}
// Phase-granularity conflict-free swizzle: fold bit4 -> {0,2}, bit5 -> {1,3}.
__device__ __forceinline__ unsigned SWZ(unsigned x) {
    return x ^ (((x >> 4) & 1u) * 5u) ^ (((x >> 5) & 1u) * 10u);
}

// Complex 4x4 gate on a quad of packed (re,im) amps.
// q_h = (-si,sr); out_g = sum_h p_h*(wr,wr) + q_h*(wi,wi). 8 ffma2/output.
__device__ __forceinline__ void gate4(u64& v0, u64& v1, u64& v2, u64& v3,
                                      const u64* __restrict__ wa,
                                      const u64* __restrict__ wb)
{
    float r0,i0,r1,i1,r2,i2,r3,i3;
    upk2(v0,r0,i0); upk2(v1,r1,i1); upk2(v2,r2,i2); upk2(v3,r3,i3);
    u64 q0 = pk2(negf(i0), r0), q1 = pk2(negf(i1), r1);
    u64 q2 = pk2(negf(i2), r2), q3 = pk2(negf(i3), r3);
    u64 o0, o1, o2, o3;
    {
        u64 a = fmul2(v0, wa[0]);  a = ffma2(q0, wb[0], a);
        a = ffma2(v1, wa[1], a);   a = ffma2(q1, wb[1], a);
        a = ffma2(v2, wa[2], a);   a = ffma2(q2, wb[2], a);
        a = ffma2(v3, wa[3], a);   a = ffma2(q3, wb[3], a);  o0 = a;
    }
    {
        u64 a = fmul2(v0, wa[4]);  a = ffma2(q0, wb[4], a);
        a = ffma2(v1, wa[5], a);   a = ffma2(q1, wb[5], a);
        a = ffma2(v2, wa[6], a);   a = ffma2(q2, wb[6], a);
        a = ffma2(v3, wa[7], a);   a = ffma2(q3, wb[7], a);  o1 = a;
    }
    {
        u64 a = fmul2(v0, wa[8]);  a = ffma2(q0, wb[8], a);
        a = ffma2(v1, wa[9], a);   a = ffma2(q1, wb[9], a);
        a = ffma2(v2, wa[10], a);  a = ffma2(q2, wb[10], a);
        a = ffma2(v3, wa[11], a);  a = ffma2(q3, wb[11], a); o2 = a;
    }
    {
        u64 a = fmul2(v0, wa[12]); a = ffma2(q0, wb[12], a);
        a = ffma2(v1, wa[13], a);  a = ffma2(q1, wb[13], a);
        a = ffma2(v2, wa[14], a);  a = ffma2(q2, wb[14], a);
        a = ffma2(v3, wa[15], a);  a = ffma2(q3, wb[15], a); o3 = a;
    }
    v0 = o0; v1 = o1; v2 = o2; v3 = o3;
}

// Two fused gate steps on a 16-amp supergroup. P0..P3 = inserted tile-bit
// positions (ascending). First gate varies group bits (0,2)=(P0,P2);
// second gate varies (1,3)=(P1,P3). All amp-array indices literal.
template <int P0, int P1, int P2, int P3>
__device__ __forceinline__ void apply_pair(float2* sm, unsigned tid,
                                           const float* __restrict__ gp0,
                                           const float* __restrict__ gp1)
{
    unsigned x = tid;
    x = ((x & ~((1u << P0) - 1u)) << 1) | (x & ((1u << P0) - 1u));
    x = ((x & ~((1u << P1) - 1u)) << 1) | (x & ((1u << P1) - 1u));
    x = ((x & ~((1u << P2) - 1u)) << 1) | (x & ((1u << P2) - 1u));
    x = ((x & ~((1u << P3) - 1u)) << 1) | (x & ((1u << P3) - 1u));

    u64 p[16];
    #pragma unroll
    for (int i = 0; i < 16; ++i) {
        unsigned off = ((i & 1)        ? (1u << P0) : 0u)
                     | (((i >> 1) & 1) ? (1u << P1) : 0u)
                     | (((i >> 2) & 1) ? (1u << P2) : 0u)
                     | (((i >> 3) & 1) ? (1u << P3) : 0u);
        float2 v = sm[SWZ(x | off)];
        p[i] = pk2(v.x, v.y);
    }

    {   // gate 0: vary (bit0,bit2) -> quads {0,1,4,5},{2,3,6,7},{8..},{10..}
        u64 wa[16], wb[16];
        #pragma unroll
        for (int k = 0; k < 16; ++k) {
            float wr = __ldg(gp0 + k), wi = __ldg(gp0 + 16 + k);
            wa[k] = pk2(wr, wr); wb[k] = pk2(wi, wi);
        }
        gate4(p[0],  p[1],  p[4],  p[5],  wa, wb);
        gate4(p[2],  p[3],  p[6],  p[7],  wa, wb);
        gate4(p[8],  p[9],  p[12], p[13], wa, wb);
        gate4(p[10], p[11], p[14], p[15], wa, wb);
    }
    {   // gate 1: vary (bit1,bit3) -> quads {0,2,8,10},{1,3,9,11},...
        u64 wa[16], wb[16];
        #pragma unroll
        for (int k = 0; k < 16; ++k) {
            float wr = __ldg(gp1 + k), wi = __ldg(gp1 + 16 + k);
            wa[k] = pk2(wr, wr); wb[k] = pk2(wi, wi);
        }
        gate4(p[0], p[2], p[8],  p[10], wa, wb);
        gate4(p[1], p[3], p[9],  p[11], wa, wb);
        gate4(p[4], p[6], p[12], p[14], wa, wb);
        gate4(p[5], p[7], p[13], p[15], wa, wb);
    }

    #pragma unroll
    for (int i = 0; i < 16; ++i) {
        unsigned off = ((i & 1)        ? (1u << P0) : 0u)
                     | (((i >> 1) & 1) ? (1u << P1) : 0u)
                     | (((i >> 2) & 1) ? (1u << P2) : 0u)
                     | (((i >> 3) & 1) ? (1u << P3) : 0u);
        float lo, hi; upk2(p[i], lo, hi);
        sm[SWZ(x | off)] = make_float2(lo, hi);
    }
}

template <int PASS>
__global__ __launch_bounds__(256, 2)
void qsim_pass(const float* __restrict__ in, float* __restrict__ out,
               const float* __restrict__ gates)
{
    __shared__ float2 sm[4096];
    const unsigned tid = threadIdx.x;
    const unsigned b = blockIdx.x;
    const unsigned hi = (PASS == 0) ? (b << 12)
                                    : (((b & 7u) << 8) | ((b >> 3) << 15));

    // ---- Stage tile: LDG.128 per plane, conflict-free STS.64 ----
    #pragma unroll
    for (int j = 0; j < 4; ++j) {
        unsigned a = (tid + 256u * j) * 4u;
        unsigned g = (PASS == 0) ? (hi | a)
                                 : (hi | ((a >> 8) << 11) | (a & 255u));
        float4 r4 = *(const float4*)(in + g);
        float4 m4 = *(const float4*)(in + NSTATE + g);
        sm[SWZ(a + 0)] = make_float2(r4.x, m4.x);
        sm[SWZ(a + 1)] = make_float2(r4.y, m4.y);
        sm[SWZ(a + 2)] = make_float2(r4.z, m4.z);
        sm[SWZ(a + 3)] = make_float2(r4.w, m4.w);
    }
    __syncthreads();

    // ---- Two fused gate pairs ----
    if (PASS == 0) apply_pair<0, 1, 7, 8>(sm, tid, gates + 0 * 32, gates + 1 * 32);
    else           apply_pair<4, 5, 8, 9>(sm, tid, gates + 4 * 32, gates + 5 * 32);
    __syncthreads();
    if (PASS == 0) apply_pair<2, 3, 9, 10>(sm, tid, gates + 2 * 32, gates + 3 * 32);
    else           apply_pair<6, 7, 10, 11>(sm, tid, gates + 6 * 32, gates + 7 * 32);
    __syncthreads();

    // ---- Write back: STG.128 per plane ----
    #pragma unroll
    for (int j = 0; j < 4; ++j) {
        unsigned a = (tid + 256u * j) * 4u;
        unsigned g = (PASS == 0) ? (hi | a)
                                 : (hi | ((a >> 8) << 11) | (a & 255u));
        float2 v0 = sm[SWZ(a + 0)], v1 = sm[SWZ(a + 1)];
        float2 v2 = sm[SWZ(a + 2)], v3 = sm[SWZ(a + 3)];
        *(float4*)(out + g)          = make_float4(v0.x, v1.x, v2.x, v3.x);
        *(float4*)(out + NSTATE + g) = make_float4(v0.y, v1.y, v2.y, v3.y);
    }
}

extern "C" void kernel_launch(void* const* d_in, const int* in_sizes, int n_in,
                              void* d_out, int out_size)
{
    const float* state = (const float*)d_in[0];   // 2 * 2^24 floats (re, im planes)
    const float* gates = (const float*)d_in[1];   // 8 * 2 * 4 * 4 floats
    float* out = (float*)d_out;

    qsim_pass<0><<<4096, 256>>>(state, out, gates);   // steps 0..3
    qsim_pass<1><<<4096, 256>>>(out, out, gates);     // steps 4..7 (in place, disjoint)
}